// round 2
// baseline (speedup 1.0000x reference)
#include <cuda_runtime.h>
#include <cuda_bf16.h>
#include <math.h>

#define BB 32
#define HH 480
#define WW 640
#define HW (HH*WW)
#define OH 34
#define OW 45
#define NC (OH*OW)      // 1530
#define K_TOP 153
#define KS 25
#define PS (KS*KS)      // 625
#define EPSV 1e-5f
#define SEG 40

// ---------------- device scratch (static, no allocations) ----------------
__device__ unsigned g_hist[BB][2][2048];
__device__ unsigned g_ncnt[BB];
__device__ unsigned g_prefix[BB][2];
__device__ unsigned g_krem[BB][2];
__device__ float    g_med[BB][2];
__device__ float    g_scalesum[BB][2];
__device__ float    g_gsum[BB];
__device__ float    g_coarse[BB][NC];
__device__ int      g_cy[BB][K_TOP];
__device__ int      g_cx[BB][K_TOP];
__device__ float    g_epsum[BB];
__device__ unsigned g_epcnt[BB];
__device__ int      g_mmode;   // 0=uint8, 1=float32, 2=int32 bool encoding

// ---------------- helpers ----------------
__device__ __forceinline__ unsigned fkey(float v){
    unsigned u = __float_as_uint(v);
    return (u & 0x80000000u) ? ~u : (u | 0x80000000u);
}
__device__ __forceinline__ float fval(unsigned u){
    unsigned o = (u & 0x80000000u) ? (u & 0x7fffffffu) : ~u;
    return __uint_as_float(o);
}
__device__ __forceinline__ bool readmask(const void* p, size_t i, int mode){
    if (mode == 0) return ((const unsigned char*)p)[i] != 0;
    if (mode == 1) return ((const float*)p)[i] != 0.0f;
    return ((const int*)p)[i] != 0;
}

// block = 256 threads assumed
__device__ __forceinline__ float blockReduceSumF(float v, float* sh8){
    int lane = threadIdx.x & 31, w = threadIdx.x >> 5;
#pragma unroll
    for (int o=16;o>0;o>>=1) v += __shfl_down_sync(0xffffffffu, v, o);
    if (lane==0) sh8[w]=v;
    __syncthreads();
    if (w==0){
        float r = (lane<8)? sh8[lane]:0.f;
#pragma unroll
        for (int o=4;o>0;o>>=1) r += __shfl_down_sync(0xffffffffu, r, o);
        if (lane==0) sh8[0]=r;
    }
    __syncthreads();
    float r = sh8[0];
    __syncthreads();
    return r;
}
__device__ __forceinline__ unsigned blockReduceSumU(unsigned v, unsigned* sh8){
    int lane = threadIdx.x & 31, w = threadIdx.x >> 5;
#pragma unroll
    for (int o=16;o>0;o>>=1) v += __shfl_down_sync(0xffffffffu, v, o);
    if (lane==0) sh8[w]=v;
    __syncthreads();
    if (w==0){
        unsigned r = (lane<8)? sh8[lane]:0u;
#pragma unroll
        for (int o=4;o>0;o>>=1) r += __shfl_down_sync(0xffffffffu, r, o);
        if (lane==0) sh8[0]=r;
    }
    __syncthreads();
    unsigned r = sh8[0];
    __syncthreads();
    return r;
}
// inclusive scan over 256 thread values
__device__ __forceinline__ unsigned blockScanInc(unsigned v, unsigned* sh8){
    int lane = threadIdx.x & 31, w = threadIdx.x >> 5;
    unsigned x = v;
#pragma unroll
    for (int o=1;o<32;o<<=1){ unsigned t=__shfl_up_sync(0xffffffffu,x,o); if(lane>=o) x+=t; }
    if (lane==31) sh8[w]=x;
    __syncthreads();
    if (w==0){
        unsigned y = (lane<8)? sh8[lane]:0u;
#pragma unroll
        for (int o=1;o<8;o<<=1){ unsigned t=__shfl_up_sync(0xffffffffu,y,o); if(lane>=o) y+=t; }
        if (lane<8) sh8[lane]=y;
    }
    __syncthreads();
    unsigned off = (w>0)? sh8[w-1]:0u;
    unsigned r = x + off;
    __syncthreads();
    return r;
}

// ---------------- kernels ----------------
__global__ void detect_kernel(const void* mask){
    __shared__ unsigned sh8[8];
    const unsigned char* m = (const unsigned char*)mask;
    unsigned c=0;
    for (int i=threadIdx.x;i<4096;i+=256) c += (m[i]!=0);
    unsigned tot = blockReduceSumU(c, sh8);
    if (threadIdx.x==0){
        g_mmode = (tot>2765)?0 : ((tot>1382)?1:2);
    }
}

__global__ void reset_kernel(){
    int i = blockIdx.x*blockDim.x + threadIdx.x;
    if (i < BB*2*2048) ((unsigned*)g_hist)[i]=0u;
    if (i < BB){
        g_ncnt[i]=0u; g_gsum[i]=0.f; g_epsum[i]=0.f; g_epcnt[i]=0u;
        g_scalesum[i][0]=0.f; g_scalesum[i][1]=0.f;
    }
}

template<int PASS>
__global__ __launch_bounds__(256) void ghist_kernel(const float* inp, const float* tgt, const void* mask){
    __shared__ unsigned sh[4096];
    __shared__ unsigned shc;
    int b = blockIdx.y;
    for (int i=threadIdx.x;i<4096;i+=256) sh[i]=0u;
    if (threadIdx.x==0) shc=0u;
    int mode = g_mmode;
    unsigned p0=0,p1=0;
    if (PASS>0){ p0=g_prefix[b][0]; p1=g_prefix[b][1]; }
    __syncthreads();
    int chunk = (HW + gridDim.x - 1)/gridDim.x;
    int s0 = blockIdx.x*chunk, e0 = min(s0+chunk, HW);
    const float* ib = inp + (size_t)b*HW;
    const float* tb = tgt + (size_t)b*HW;
    unsigned lc=0;
    for (int i=s0+threadIdx.x; i<e0; i+=256){
        if (readmask(mask, (size_t)b*HW+i, mode)){
            lc++;
            unsigned u0 = fkey(ib[i]);
            unsigned u1 = fkey(tb[i]);
            if (PASS==0){
                atomicAdd(&sh[u0>>21],1u);
                atomicAdd(&sh[2048+(u1>>21)],1u);
            } else if (PASS==1){
                if ((u0>>21)==p0) atomicAdd(&sh[(u0>>10)&2047],1u);
                if ((u1>>21)==p1) atomicAdd(&sh[2048+((u1>>10)&2047)],1u);
            } else {
                if ((u0>>10)==p0) atomicAdd(&sh[u0&1023],1u);
                if ((u1>>10)==p1) atomicAdd(&sh[2048+(u1&1023)],1u);
            }
        }
    }
    if (PASS==0 && lc) atomicAdd(&shc, lc);
    __syncthreads();
    for (int i=threadIdx.x;i<4096;i+=256){
        unsigned v = sh[i];
        if (v) atomicAdd(&g_hist[b][i>>11][i&2047], v);
    }
    if (PASS==0 && threadIdx.x==0 && shc) atomicAdd(&g_ncnt[b], shc);
}

template<int PASS>
__global__ __launch_bounds__(256) void gselect_kernel(){
    int a = blockIdx.x, b = blockIdx.y, tid = threadIdx.x;
    __shared__ unsigned sh8[8];
    __shared__ unsigned shbin, shbefore;
    unsigned h[8];
    unsigned s = 0;
#pragma unroll
    for (int j=0;j<8;j++){ h[j]=g_hist[b][a][tid*8+j]; s+=h[j]; }
    unsigned inc = blockScanInc(s, sh8);
    unsigned exc = inc - s;
    unsigned n = g_ncnt[b];
    unsigned k = (PASS==0) ? (n ? (n-1u)/2u : 0u) : g_krem[b][a];
    if (exc<=k && k<inc){
        unsigned c = exc; int bin = tid*8;
#pragma unroll
        for (int j=0;j<8;j++){
            if (k < c + h[j]){ bin = tid*8+j; break; }
            c += h[j];
        }
        shbin = (unsigned)bin; shbefore = c;
    }
    __syncthreads();
    if (tid==0){
        if (PASS==0){ g_prefix[b][a]=shbin; g_krem[b][a]=k-shbefore; }
        else if (PASS==1){ g_prefix[b][a]=(g_prefix[b][a]<<11)|shbin; g_krem[b][a]=k-shbefore; }
        else {
            unsigned bits = (g_prefix[b][a]<<10)|shbin;
            g_med[b][a] = n ? fval(bits) : 0.f;
        }
    }
    // zero histogram for next pass / next replay
#pragma unroll
    for (int j=0;j<8;j++) g_hist[b][a][tid*8+j]=0u;
}

__global__ __launch_bounds__(256) void gscale_kernel(const float* inp, const float* tgt, const void* mask){
    __shared__ float sh8[8];
    int b = blockIdx.y, mode = g_mmode;
    float m0 = g_med[b][0], m1 = g_med[b][1];
    int chunk = (HW + gridDim.x - 1)/gridDim.x;
    int s0 = blockIdx.x*chunk, e0 = min(s0+chunk, HW);
    const float* ib = inp + (size_t)b*HW;
    const float* tb = tgt + (size_t)b*HW;
    float a0=0.f, a1=0.f;
    for (int i=s0+threadIdx.x; i<e0; i+=256){
        if (readmask(mask, (size_t)b*HW+i, mode)){
            a0 += fabsf(ib[i]-m0);
            a1 += fabsf(tb[i]-m1);
        }
    }
    float r0 = blockReduceSumF(a0, sh8);
    float r1 = blockReduceSumF(a1, sh8);
    if (threadIdx.x==0){
        if (r0!=0.f) atomicAdd(&g_scalesum[b][0], r0);
        if (r1!=0.f) atomicAdd(&g_scalesum[b][1], r1);
    }
}

__global__ __launch_bounds__(256) void gerr_kernel(const float* inp, const float* tgt, const void* mask){
    __shared__ float sh8[8];
    int b = blockIdx.y, mode = g_mmode;
    float fn = fmaxf((float)g_ncnt[b], 1.f);
    float m0 = g_med[b][0], m1 = g_med[b][1];
    float d0 = fmaxf(g_scalesum[b][0]/fn, EPSV);
    float d1 = fmaxf(g_scalesum[b][1]/fn, EPSV);
    int chunk = (HW + gridDim.x - 1)/gridDim.x;
    int s0 = blockIdx.x*chunk, e0 = min(s0+chunk, HW);
    const float* ib = inp + (size_t)b*HW;
    const float* tb = tgt + (size_t)b*HW;
    float acc=0.f;
    for (int i=s0+threadIdx.x; i<e0; i+=256){
        if (readmask(mask, (size_t)b*HW+i, mode)){
            float gi = (ib[i]-m0)/d0;
            float gt = (tb[i]-m1)/d1;
            acc += fmaxf(fabsf(gi-gt), EPSV);
        }
    }
    float r = blockReduceSumF(acc, sh8);
    if (threadIdx.x==0 && r!=0.f) atomicAdd(&g_gsum[b], r);
}

__device__ float edge_at(const float* img, const void* vmask, int b, int y, int x, int mode){
    if (y<3 || y>=HH-3 || x<3 || x>=WW-3) return 0.f;
    // eroded validity: all 9 neighbors set (in-bounds guaranteed here)
    size_t vb = (size_t)b*HW;
#pragma unroll
    for (int dy=-1;dy<=1;dy++)
#pragma unroll
        for (int dx=-1;dx<=1;dx++)
            if (!readmask(vmask, vb + (size_t)(y+dy)*WW + (x+dx), mode)) return 0.f;
    float sgx=0.f, sgy=0.f;
#pragma unroll
    for (int c=0;c<3;c++){
        const float* p = img + ((size_t)b*3 + c)*HW;
        float a00=p[(y-1)*WW+x-1], a01=p[(y-1)*WW+x], a02=p[(y-1)*WW+x+1];
        float a10=p[y*WW+x-1],                         a12=p[y*WW+x+1];
        float a20=p[(y+1)*WW+x-1], a21=p[(y+1)*WW+x], a22=p[(y+1)*WW+x+1];
        float gx = (a02 - a00) + 2.f*(a12 - a10) + (a22 - a20);
        float gy = (a20 - a00) + 2.f*(a21 - a01) + (a22 - a02);
        gx *= 0.125f; gy *= 0.125f;
        sgx += gx*gx; sgy += gy*gy;
    }
    float gxr = sqrtf(sgx/3.f);
    float gyr = sqrtf(sgy/3.f);
    return sqrtf(gxr*gxr + gyr*gyr);
}

__global__ void coarse_kernel(const float* image, const void* vmask){
    int b = blockIdx.y;
    int j = blockIdx.x*blockDim.x + threadIdx.x;
    if (j >= NC) return;
    int mode = g_mmode;
    int oy = j/OW, ox = j%OW;
    float sy = (float)(480.0/34.0);
    float sx = (float)(640.0/45.0);
    float cy = fminf(fmaxf(((float)oy + 0.5f)*sy - 0.5f, 0.f), (float)(HH-1));
    float cx = fminf(fmaxf(((float)ox + 0.5f)*sx - 0.5f, 0.f), (float)(WW-1));
    int y0 = (int)floorf(cy); int y1 = min(y0+1, HH-1); float wy = cy - (float)y0;
    int x0 = (int)floorf(cx); int x1 = min(x0+1, WW-1); float wx = cx - (float)x0;
    float e00 = edge_at(image, vmask, b, y0, x0, mode);
    float e01 = edge_at(image, vmask, b, y0, x1, mode);
    float e10 = edge_at(image, vmask, b, y1, x0, mode);
    float e11 = edge_at(image, vmask, b, y1, x1, mode);
    float val = ((e00*(1.f-wy))*(1.f-wx)) + ((e01*(1.f-wy))*wx)
              + ((e10*wy)*(1.f-wx)) + ((e11*wy)*wx);
    g_coarse[b][j] = val;
}

__global__ __launch_bounds__(1024) void topk_kernel(){
    __shared__ unsigned long long key[2048];
    int b = blockIdx.x, tid = threadIdx.x;
    for (int i=tid;i<2048;i+=1024){
        if (i < NC){
            float v = g_coarse[b][i];
            key[i] = ((unsigned long long)fkey(v) << 32) | (unsigned)(0xFFFFFFFFu - (unsigned)i);
        } else key[i] = 0ull;
    }
    __syncthreads();
    for (int size=2; size<=2048; size<<=1){
        for (int stride=size>>1; stride>0; stride>>=1){
            for (int e=tid; e<2048; e+=1024){
                int p = e ^ stride;
                if (p > e){
                    bool up = (e & size)==0;
                    unsigned long long A = key[e], Bk = key[p];
                    bool sw = up ? (A < Bk) : (A > Bk);   // descending overall
                    if (sw){ key[e]=Bk; key[p]=A; }
                }
            }
            __syncthreads();
        }
    }
    if (tid < K_TOP){
        unsigned idx = 0xFFFFFFFFu - (unsigned)(key[tid] & 0xFFFFFFFFull);
        g_cy[b][tid] = (int)(idx/OW)*14;
        g_cx[b][tid] = (int)(idx%OW)*14;
    }
}

__global__ __launch_bounds__(256) void patch_kernel(const float* inp, const float* tgt, const void* mask){
    __shared__ float s_in[PS], s_tg[PS];
    __shared__ unsigned char s_m[PS];
    __shared__ unsigned sh_hist[512];
    __shared__ unsigned sh8u[8];
    __shared__ float sh8f[8];
    __shared__ unsigned sh_pref[2], sh_k[2];
    int b = blockIdx.y, p = blockIdx.x, tid = threadIdx.x;
    int mode = g_mmode;
    int cy = g_cy[b][p], cx = g_cx[b][p];
    unsigned lc = 0;
    for (int i=tid;i<PS;i+=256){
        int dy = i/KS - 12, dx = i%KS - 12;
        int y = cy+dy, x = cx+dx;
        bool inb = (y>=0 && y<HH && x>=0 && x<WW);
        bool m = false; float vi=0.f, vt=0.f;
        if (inb){
            size_t idx = (size_t)b*HW + (size_t)y*WW + x;
            m = readmask(mask, idx, mode);
            if (m){ vi = inp[idx]; vt = tgt[idx]; }
        }
        s_m[i] = m; s_in[i] = vi; s_tg[i] = vt;
        lc += m;
    }
    __syncthreads();
    unsigned n = blockReduceSumU(lc, sh8u);

    unsigned k0 = n ? (n-1u)>>1 : 0u, k1 = k0;
    unsigned pref0 = 0u, pref1 = 0u;
    if (n){
#pragma unroll
        for (int pass=0; pass<4; pass++){
            const int shift = 24 - 8*pass;
            sh_hist[tid] = 0u;          // FIX: zero ALL 512 entries every pass
            sh_hist[tid+256] = 0u;
            __syncthreads();
            for (int i=tid;i<PS;i+=256){
                if (s_m[i]){
                    unsigned u0 = fkey(s_in[i]);
                    unsigned u1 = fkey(s_tg[i]);
                    bool f0 = (pass==0) || ((u0 >> (shift+8)) == pref0);
                    bool f1 = (pass==0) || ((u1 >> (shift+8)) == pref1);
                    if (f0) atomicAdd(&sh_hist[((u0>>shift)&255)*2    ], 1u);
                    if (f1) atomicAdd(&sh_hist[((u1>>shift)&255)*2 + 1], 1u);
                }
            }
            __syncthreads();
            unsigned s = sh_hist[tid*2] + (sh_hist[tid*2+1] << 16);
            unsigned inc = blockScanInc(s, sh8u);
            unsigned exc = inc - s;
            unsigned e0 = exc & 0xffffu, i0 = inc & 0xffffu;
            unsigned e1 = exc >> 16,    i1 = inc >> 16;
            if (e0<=k0 && k0<i0){ sh_pref[0] = (pref0<<8)|(unsigned)tid; sh_k[0] = k0 - e0; }
            if (e1<=k1 && k1<i1){ sh_pref[1] = (pref1<<8)|(unsigned)tid; sh_k[1] = k1 - e1; }
            __syncthreads();
            pref0 = sh_pref[0]; pref1 = sh_pref[1];
            k0 = sh_k[0]; k1 = sh_k[1];
            __syncthreads();
        }
    }
    float med0 = n ? fval(pref0) : 0.f;
    float med1 = n ? fval(pref1) : 0.f;

    float a0=0.f, a1=0.f;
    for (int i=tid;i<PS;i+=256){
        if (s_m[i]){
            a0 += fabsf(s_in[i]-med0);
            a1 += fabsf(s_tg[i]-med1);
        }
    }
    float sum0 = blockReduceSumF(a0, sh8f);
    float sum1 = blockReduceSumF(a1, sh8f);
    float fn = fmaxf((float)n, 1.f);
    float d0 = fmaxf(sum0/fn, EPSV);
    float d1 = fmaxf(sum1/fn, EPSV);

    float e = 0.f;
    for (int i=tid;i<PS;i+=256){
        if (s_m[i]){
            float gi = (s_in[i]-med0)/d0;
            float gt = (s_tg[i]-med1)/d1;
            e += fmaxf(fabsf(gi-gt), EPSV);
        }
    }
    float esum = blockReduceSumF(e, sh8f);
    if (tid==0 && n>=4u){
        float ep = sqrtf(fmaxf(esum/fn, EPSV));
        atomicAdd(&g_epsum[b], ep);
        atomicAdd(&g_epcnt[b], 1u);
    }
}

__global__ void final_kernel(float* out){
    int b = threadIdx.x;
    if (b >= BB) return;
    float ep = g_epsum[b] / fmaxf((float)g_epcnt[b], 1.f);
    float fn = fmaxf((float)g_ncnt[b], 1.f);
    float eg = sqrtf(fmaxf(g_gsum[b]/fn, EPSV));
    out[b] = 0.5f*(ep + eg);
}

// ---------------- launch ----------------
extern "C" void kernel_launch(void* const* d_in, const int* in_sizes, int n_in,
                              void* d_out, int out_size) {
    const float* inp  = (const float*)d_in[0];
    const float* tgt  = (const float*)d_in[1];
    const void*  mask = d_in[2];
    const float* img  = (const float*)d_in[3];
    const void*  vmsk = d_in[4];
    float* out = (float*)d_out;

    detect_kernel<<<1,256>>>(mask);
    reset_kernel<<<(BB*2*2048 + 255)/256, 256>>>();

    dim3 gseg(SEG, BB);
    dim3 gsel(2, BB);
    ghist_kernel<0><<<gseg,256>>>(inp, tgt, mask);
    gselect_kernel<0><<<gsel,256>>>();
    ghist_kernel<1><<<gseg,256>>>(inp, tgt, mask);
    gselect_kernel<1><<<gsel,256>>>();
    ghist_kernel<2><<<gseg,256>>>(inp, tgt, mask);
    gselect_kernel<2><<<gsel,256>>>();
    gscale_kernel<<<gseg,256>>>(inp, tgt, mask);
    gerr_kernel<<<gseg,256>>>(inp, tgt, mask);

    coarse_kernel<<<dim3((NC+127)/128, BB),128>>>(img, vmsk);
    topk_kernel<<<BB,1024>>>();
    patch_kernel<<<dim3(K_TOP, BB),256>>>(inp, tgt, mask);

    final_kernel<<<1,32>>>(out);
}